// round 5
// baseline (speedup 1.0000x reference)
#include <cuda_runtime.h>
#include <cuda_fp16.h>

// Problem constants
#define NW      16384   // words
#define LCH     16      // chars per word
#define CEMB    64      // char emb dim
#define CO      256     // conv out channels
#define DEMB    300     // word emb dim
#define OUTW    556     // 256 + 300
#define OCHUNK  64      // channels per block (blockIdx.y in {0..3})

// Precomputed conv tables (fp16): M[k][c][o] = sum_e char_emb[c,e]*conv_w[o,e,k]
__device__ __half g_Mh[3 * 128 * 256];

// ---------------------------------------------------------------------------
// Kernel 1: build tables. grid = 256 (o), block = 128 (c).
// conv_w reads are warp-UNIFORM (broadcast) -> 1 wavefront per load.
// ---------------------------------------------------------------------------
__global__ void build_tables_kernel(const float* __restrict__ ce_w,
                                    const float* __restrict__ conv_w) {
    __shared__ float se[64 * 128];   // se[e*128 + c]
    const int o = blockIdx.x;
    const int c = threadIdx.x;

    for (int i = threadIdx.x; i < 128 * 64; i += 128) {
        int cc = i >> 6;
        int e  = i & 63;
        se[e * 128 + cc] = ce_w[i];   // coalesced read, conflict-free write
    }
    __syncthreads();

    const float* wp = conv_w + o * (CEMB * 3);   // uniform across the block
    float a0 = 0.f, a1 = 0.f, a2 = 0.f;
#pragma unroll
    for (int e = 0; e < CEMB; ++e) {
        float w0 = wp[e * 3 + 0];    // broadcast
        float w1 = wp[e * 3 + 1];
        float w2 = wp[e * 3 + 2];
        float s  = se[e * 128 + c];
        a0 = fmaf(s, w0, a0);
        a1 = fmaf(s, w1, a1);
        a2 = fmaf(s, w2, a2);
    }
    g_Mh[(0 * 128 + c) * 256 + o] = __float2half_rn(a0);
    g_Mh[(1 * 128 + c) * 256 + o] = __float2half_rn(a1);
    g_Mh[(2 * 128 + c) * 256 + o] = __float2half_rn(a2);
}

// ---------------------------------------------------------------------------
// Kernel 2: main. grid = (148, 4), block = 384, 48 KB dyn smem, 4 CTAs/SM.
// 48 warps/SM (75% occ). Warp = one word; lane = 2 channels (half2, LDS.32:
// 32 lanes x 4B = 128B = 1 wavefront per table load -> same total crossbar
// traffic as the 2-chunk version, double the occupancy).
// blockIdx.y in {0..3} selects the 64-channel chunk and a word-emb slice.
// ---------------------------------------------------------------------------
extern "C" __global__ void __launch_bounds__(384, 4)
wordchar_main_kernel(const int* __restrict__ X,
                     const int* __restrict__ Xword,
                     const float* __restrict__ conv_b,
                     const float* __restrict__ wemb,
                     float* __restrict__ out) {
    extern __shared__ __align__(16) char smem_raw[];
    __half2* Ms  = reinterpret_cast<__half2*>(smem_raw);   // [(k*128+c)*32 + lane]
    uint4*  Ms16 = reinterpret_cast<uint4*>(smem_raw);

    const int chunk  = blockIdx.y;
    const int o_base = chunk * OCHUNK;

    // stage this chunk's table: 3*128 rows x 128B (8 uint4 per row)
    {
        const uint4* Mg16 = reinterpret_cast<const uint4*>(g_Mh);
        const int n16 = 3 * 128 * 8;                   // 3072
        for (int i = threadIdx.x; i < n16; i += blockDim.x) {
            int row = i >> 3;                          // (k*128 + c)
            int j   = i & 7;
            Ms16[i] = Mg16[row * 32 + chunk * 8 + j];
        }
    }
    __syncthreads();

    const int warp   = threadIdx.x >> 5;
    const int lane   = threadIdx.x & 31;
    const int gwarp  = blockIdx.x * 12 + warp;
    const int nwarps = gridDim.x * 12;

    const float2 b2 = *reinterpret_cast<const float2*>(conv_b + o_base + lane * 2);

    // this chunk's slice of the 75-float4 word-embedding copy
    // chunks 0..2: 19 each; chunk 3: 18
    const int j_lo = chunk * 19;
    const int j_hi = (chunk == 3) ? 75 : j_lo + 19;

    const __half2 zero = __float2half2_rn(0.f);

    for (int w = gwarp; w < NW; w += nwarps) {
        const int4* xr = reinterpret_cast<const int4*>(X + w * LCH);
        int4 x0 = xr[0], x1 = xr[1], x2 = xr[2], x3 = xr[3];
        int xs[16];
        xs[0]=x0.x; xs[1]=x0.y; xs[2]=x0.z; xs[3]=x0.w;
        xs[4]=x1.x; xs[5]=x1.y; xs[6]=x1.z; xs[7]=x1.w;
        xs[8]=x2.x; xs[9]=x2.y; xs[10]=x2.z; xs[11]=x2.w;
        xs[12]=x3.x; xs[13]=x3.y; xs[14]=x3.z; xs[15]=x3.w;

        // kick off this chunk's word-embedding slice early (independent)
        const int wi = Xword[w];
        const float4* src = reinterpret_cast<const float4*>(wemb + (size_t)wi * DEMB);
        float4* dst = reinterpret_cast<float4*>(out + (size_t)w * OUTW + CO);
        float4 e0;
        const int j0 = j_lo + lane;
        const bool p0 = (j0 < j_hi);
        if (p0) e0 = src[j0];

        // carry-chain sliding window:
        //   y[t] = M2[x_t] + c1,  c1' = M1[x_t] + c0,  c0' = M0[x_t]
        __half2 maxs, c0 = zero, c1 = zero;
#pragma unroll
        for (int t = 0; t < 16; ++t) {
            int cc = xs[t];
            __half2 m0 = Ms[(0 * 128 + cc) * 32 + lane];
            __half2 m1 = Ms[(1 * 128 + cc) * 32 + lane];
            __half2 m2 = Ms[(2 * 128 + cc) * 32 + lane];
            __half2 y  = __hadd2(m2, c1);
            maxs = (t == 0) ? y : __hmax2(maxs, y);
            c1 = __hadd2(m1, c0);
            c0 = m0;
        }
        maxs = __hmax2(maxs, c1);   // t = 16
        maxs = __hmax2(maxs, c0);   // t = 17

        // fp32 bias + relu + store (2 floats)
        float2 f = __half22float2(maxs);
        float2 r;
        r.x = fmaxf(f.x + b2.x, 0.f);
        r.y = fmaxf(f.y + b2.y, 0.f);
        *reinterpret_cast<float2*>(out + (size_t)w * OUTW + o_base + lane * 2) = r;

        // complete this chunk's share of the embedding copy
        if (p0) dst[j0] = e0;
    }
}

// ---------------------------------------------------------------------------
// Launch
// ---------------------------------------------------------------------------
extern "C" void kernel_launch(void* const* d_in, const int* in_sizes, int n_in,
                              void* d_out, int out_size) {
    const int*   X        = (const int*)  d_in[0];   // [16384,16]
    const int*   X_word   = (const int*)  d_in[1];   // [16384]
    const float* char_emb = (const float*)d_in[2];   // [128,64]
    const float* conv_w   = (const float*)d_in[3];   // [256,64,3]
    const float* conv_b   = (const float*)d_in[4];   // [256]
    const float* word_emb = (const float*)d_in[5];   // [50000,300]
    float*       out      = (float*)d_out;           // [16384,556]

    build_tables_kernel<<<256, 128>>>(char_emb, conv_w);

    const int smem = 3 * 128 * OCHUNK * (int)sizeof(__half);   // 49152
    cudaFuncSetAttribute(wordchar_main_kernel,
                         cudaFuncAttributeMaxDynamicSharedMemorySize, smem);
    dim3 grid(148, 4);
    wordchar_main_kernel<<<grid, 384, smem>>>(X, X_word, conv_b, word_emb, out);
}

// round 6
// speedup vs baseline: 1.0216x; 1.0216x over previous
#include <cuda_runtime.h>
#include <cuda_fp16.h>

// Problem constants
#define NW      16384   // words
#define LCH     16      // chars per word
#define CEMB    64      // char emb dim
#define CO      256     // conv out channels
#define DEMB    300     // word emb dim
#define OUTW    556     // 256 + 300
#define OCHUNK  128     // channels per block (blockIdx.y in {0,1})

// Precomputed conv tables (fp16): M[k][c][o] = sum_e char_emb[c,e]*conv_w[o,e,k]
__device__ __half g_Mh[3 * 128 * 256];

// ---------------------------------------------------------------------------
// Kernel 1: build tables. grid = 256 (o), block = 128 (c).
// conv_w reads are warp-UNIFORM (broadcast) -> 1 wavefront per load.
// ---------------------------------------------------------------------------
__global__ void build_tables_kernel(const float* __restrict__ ce_w,
                                    const float* __restrict__ conv_w) {
    __shared__ float se[64 * 128];   // se[e*128 + c]
    const int o = blockIdx.x;
    const int c = threadIdx.x;

    for (int i = threadIdx.x; i < 128 * 64; i += 128) {
        int cc = i >> 6;
        int e  = i & 63;
        se[e * 128 + cc] = ce_w[i];   // coalesced read, conflict-free write
    }
    __syncthreads();

    const float* wp = conv_w + o * (CEMB * 3);   // uniform across the block
    float a0 = 0.f, a1 = 0.f, a2 = 0.f;
#pragma unroll
    for (int e = 0; e < CEMB; ++e) {
        float w0 = wp[e * 3 + 0];    // broadcast
        float w1 = wp[e * 3 + 1];
        float w2 = wp[e * 3 + 2];
        float s  = se[e * 128 + c];
        a0 = fmaf(s, w0, a0);
        a1 = fmaf(s, w1, a1);
        a2 = fmaf(s, w2, a2);
    }
    g_Mh[(0 * 128 + c) * 256 + o] = __float2half_rn(a0);
    g_Mh[(1 * 128 + c) * 256 + o] = __float2half_rn(a1);
    g_Mh[(2 * 128 + c) * 256 + o] = __float2half_rn(a2);
}

// ---------------------------------------------------------------------------
// Kernel 2: main. grid = (148, 2), block = 512, 96 KB dyn smem, 2 CTAs/SM.
// Warp = one word; lane = 4 channels (H4). Smem table repacked per char:
//   row c (768 B) = [ lane0:{m0,m1} lane1:{m0,m1} ... (512 B) | m2 (256 B) ]
// so the 3 table reads per t are ONE LDS.128 + ONE LDS.64 off base c*768.
// ---------------------------------------------------------------------------
struct H4 { __half2 a, b; };

__device__ __forceinline__ H4 h4add(H4 x, H4 y) {
    H4 r; r.a = __hadd2(x.a, y.a); r.b = __hadd2(x.b, y.b); return r;
}
__device__ __forceinline__ H4 h4max(H4 x, H4 y) {
    H4 r; r.a = __hmax2(x.a, y.a); r.b = __hmax2(x.b, y.b); return r;
}

extern "C" __global__ void __launch_bounds__(512, 2)
wordchar_main_kernel(const int* __restrict__ X,
                     const int* __restrict__ Xword,
                     const float* __restrict__ conv_b,
                     const float* __restrict__ wemb,
                     float* __restrict__ out) {
    extern __shared__ __align__(16) char smem_raw[];

    const int half_id = blockIdx.y;
    const int o_base  = half_id * OCHUNK;

    // ---- stage + repack table: dest uint2 index c*96 + s,
    //      s<64: lane=s>>1, k=s&1 (m0/m1 interleaved); s>=64: lane=s-64, k=2
    {
        const uint2* Mg2 = reinterpret_cast<const uint2*>(g_Mh);  // 4 halves each
        uint2* Ms2 = reinterpret_cast<uint2*>(smem_raw);
        const int o4 = o_base >> 2;            // offset in uint2 units within a row
        const int ntot = 128 * 96;             // 12288
        for (int i = threadIdx.x; i < ntot; i += blockDim.x) {
            int c = i / 96;
            int s = i - c * 96;
            int k, ln;
            if (s < 64) { ln = s >> 1; k = s & 1; }
            else        { ln = s - 64; k = 2;     }
            Ms2[i] = Mg2[(k * 128 + c) * 64 + o4 + ln];
        }
    }
    __syncthreads();

    const int warp   = threadIdx.x >> 5;
    const int lane   = threadIdx.x & 31;
    const int gwarp  = blockIdx.x * 16 + warp;
    const int nwarps = gridDim.x * 16;

    const float4 b4 = *reinterpret_cast<const float4*>(conv_b + o_base + lane * 4);

    // per-lane byte offsets within a 768B char row
    const int off01 = lane * 16;         // packed m0|m1 (16B)
    const int off2  = 512 + lane * 8;    // m2 (8B)

    // this half's slice of the 75-float4 word-embedding copy
    const int j_lo = (half_id == 0) ? 0  : 38;
    const int j_hi = (half_id == 0) ? 38 : 75;

    const H4 zero = { __float2half2_rn(0.f), __float2half2_rn(0.f) };

    for (int w = gwarp; w < NW; w += nwarps) {
        const int4* xr = reinterpret_cast<const int4*>(X + w * LCH);
        int4 x0 = xr[0], x1 = xr[1], x2 = xr[2], x3 = xr[3];
        int xs[16];
        xs[0]=x0.x; xs[1]=x0.y; xs[2]=x0.z; xs[3]=x0.w;
        xs[4]=x1.x; xs[5]=x1.y; xs[6]=x1.z; xs[7]=x1.w;
        xs[8]=x2.x; xs[9]=x2.y; xs[10]=x2.z; xs[11]=x2.w;
        xs[12]=x3.x; xs[13]=x3.y; xs[14]=x3.z; xs[15]=x3.w;

        // kick off the word-embedding gather early (independent of conv)
        const int wi = Xword[w];
        const float4* src = reinterpret_cast<const float4*>(wemb + (size_t)wi * DEMB);
        float4* dst = reinterpret_cast<float4*>(out + (size_t)w * OUTW + CO);
        float4 e0, e1;
        int j0 = j_lo + lane;
        int j1 = j_lo + 32 + lane;
        bool p0 = (j0 < j_hi);
        bool p1 = (j1 < j_hi);
        if (p0) e0 = src[j0];
        if (p1) e1 = src[j1];

        // carry-chain sliding window:
        //   y[t] = M2[x_t] + c1,  c1' = M1[x_t] + c0,  c0' = M0[x_t]
        H4 maxs, c0 = zero, c1 = zero;
#pragma unroll
        for (int t = 0; t < 16; ++t) {
            const char* rowp = smem_raw + xs[t] * 768;
            uint4 p01 = *reinterpret_cast<const uint4*>(rowp + off01);
            H4 m2     = *reinterpret_cast<const H4*>(rowp + off2);
            H4 m0, m1;
            m0.a = *reinterpret_cast<__half2*>(&p01.x);
            m0.b = *reinterpret_cast<__half2*>(&p01.y);
            m1.a = *reinterpret_cast<__half2*>(&p01.z);
            m1.b = *reinterpret_cast<__half2*>(&p01.w);
            H4 y  = h4add(m2, c1);
            maxs  = (t == 0) ? y : h4max(maxs, y);
            c1 = h4add(m1, c0);
            c0 = m0;
        }
        maxs = h4max(maxs, c1);   // t = 16
        maxs = h4max(maxs, c0);   // t = 17

        // fp32 bias + relu + store
        float2 f0 = __half22float2(maxs.a);
        float2 f1 = __half22float2(maxs.b);
        float4 r;
        r.x = fmaxf(f0.x + b4.x, 0.f);
        r.y = fmaxf(f0.y + b4.y, 0.f);
        r.z = fmaxf(f1.x + b4.z, 0.f);
        r.w = fmaxf(f1.y + b4.w, 0.f);
        *reinterpret_cast<float4*>(out + (size_t)w * OUTW + o_base + lane * 4) = r;

        // complete this half's share of the embedding copy
        if (p0) dst[j0] = e0;
        if (p1) dst[j1] = e1;
    }
}

// ---------------------------------------------------------------------------
// Launch
// ---------------------------------------------------------------------------
extern "C" void kernel_launch(void* const* d_in, const int* in_sizes, int n_in,
                              void* d_out, int out_size) {
    const int*   X        = (const int*)  d_in[0];   // [16384,16]
    const int*   X_word   = (const int*)  d_in[1];   // [16384]
    const float* char_emb = (const float*)d_in[2];   // [128,64]
    const float* conv_w   = (const float*)d_in[3];   // [256,64,3]
    const float* conv_b   = (const float*)d_in[4];   // [256]
    const float* word_emb = (const float*)d_in[5];   // [50000,300]
    float*       out      = (float*)d_out;           // [16384,556]

    build_tables_kernel<<<256, 128>>>(char_emb, conv_w);

    const int smem = 128 * 768;                       // 98304 (96 KB)
    cudaFuncSetAttribute(wordchar_main_kernel,
                         cudaFuncAttributeMaxDynamicSharedMemorySize, smem);
    dim3 grid(148, 2);
    wordchar_main_kernel<<<grid, 512, smem>>>(X, X_word, conv_b, word_emb, out);
}

// round 7
// speedup vs baseline: 1.1837x; 1.1587x over previous
#include <cuda_runtime.h>
#include <cuda_fp16.h>

// Problem constants
#define NW      16384   // words
#define LCH     16      // chars per word
#define CEMB    64      // char emb dim
#define CO      256     // conv out channels
#define DEMB    300     // word emb dim
#define OUTW    556     // 256 + 300
#define OCHUNK  128     // channels per block (blockIdx.y in {0,1})

// Precomputed conv tables (fp16): M[k][c][o] = sum_e char_emb[c,e]*conv_w[o,e,k]
__device__ __half g_Mh[3 * 128 * 256];

// ---------------------------------------------------------------------------
// Kernel 1: build tables. grid = 256 (o), block = 128 (c).
// conv_w reads warp-uniform; se padded to 130 floats/row to kill STS conflicts.
// ---------------------------------------------------------------------------
__global__ void build_tables_kernel(const float* __restrict__ ce_w,
                                    const float* __restrict__ conv_w) {
    __shared__ float se[64 * 130];   // se[e*130 + c], padded rows
    const int o = blockIdx.x;
    const int c = threadIdx.x;

    for (int i = threadIdx.x; i < 128 * 64; i += 128) {
        int cc = i >> 6;
        int e  = i & 63;
        se[e * 130 + cc] = ce_w[i];   // coalesced read; 2-way STS conflict max
    }
    __syncthreads();

    const float* wp = conv_w + o * (CEMB * 3);   // uniform across the block
    float a0 = 0.f, a1 = 0.f, a2 = 0.f;
#pragma unroll
    for (int e = 0; e < CEMB; ++e) {
        float w0 = wp[e * 3 + 0];    // broadcast
        float w1 = wp[e * 3 + 1];
        float w2 = wp[e * 3 + 2];
        float s  = se[e * 130 + c];
        a0 = fmaf(s, w0, a0);
        a1 = fmaf(s, w1, a1);
        a2 = fmaf(s, w2, a2);
    }
    g_Mh[(0 * 128 + c) * 256 + o] = __float2half_rn(a0);
    g_Mh[(1 * 128 + c) * 256 + o] = __float2half_rn(a1);
    g_Mh[(2 * 128 + c) * 256 + o] = __float2half_rn(a2);
}

// ---------------------------------------------------------------------------
// Kernel 2: main. grid = (148, 2), block = 640, 96 KB dyn smem, 2 CTAs/SM
// -> 40 warps/SM (62% occ). Warp = one word; lane = 4 channels (H4).
// Smem layout: char row c = 768 B: [k=0: 32 lanes x 8B][k=1][k=2].
// Chars packed 4-per-uint32 in registers.
// ---------------------------------------------------------------------------
struct H4 { __half2 a, b; };

__device__ __forceinline__ H4 h4add(H4 x, H4 y) {
    H4 r; r.a = __hadd2(x.a, y.a); r.b = __hadd2(x.b, y.b); return r;
}
__device__ __forceinline__ H4 h4max(H4 x, H4 y) {
    H4 r; r.a = __hmax2(x.a, y.a); r.b = __hmax2(x.b, y.b); return r;
}

extern "C" __global__ void __launch_bounds__(640, 2)
wordchar_main_kernel(const int* __restrict__ X,
                     const int* __restrict__ Xword,
                     const float* __restrict__ conv_b,
                     const float* __restrict__ wemb,
                     float* __restrict__ out) {
    extern __shared__ __align__(16) char smem_raw[];

    const int half_id = blockIdx.y;
    const int o_base  = half_id * OCHUNK;

    // stage table into [c][k][lane] rows of 768 B
    {
        const uint2* Mg2 = reinterpret_cast<const uint2*>(g_Mh);  // 4 halves each
        uint2* Ms2 = reinterpret_cast<uint2*>(smem_raw);
        const int o4 = o_base >> 2;
        const int ntot = 128 * 96;             // 12288 uint2
        for (int i = threadIdx.x; i < ntot; i += blockDim.x) {
            int c  = i / 96;
            int s  = i - c * 96;
            int k  = s >> 5;
            int ln = s & 31;
            Ms2[i] = Mg2[(k * 128 + c) * 64 + o4 + ln];
        }
    }
    __syncthreads();

    const int warp   = threadIdx.x >> 5;
    const int lane   = threadIdx.x & 31;
    const int gwarp  = blockIdx.x * 20 + warp;
    const int nwarps = gridDim.x * 20;

    const float4 b4 = *reinterpret_cast<const float4*>(conv_b + o_base + lane * 4);
    const char* Ms_lane = smem_raw + lane * 8;     // fold lane offset into base

    // this half's slice of the 75-float4 word-embedding copy
    const int j_lo = (half_id == 0) ? 0  : 38;
    const int j_hi = (half_id == 0) ? 38 : 75;

    const H4 zero = { __float2half2_rn(0.f), __float2half2_rn(0.f) };

    for (int w = gwarp; w < NW; w += nwarps) {
        // load 16 chars, pack 4 per register (chars < 128 fit a byte)
        const int4* xr = reinterpret_cast<const int4*>(X + w * LCH);
        int4 x0 = xr[0], x1 = xr[1], x2 = xr[2], x3 = xr[3];
        unsigned pk[4];
        pk[0] = (unsigned)x0.x | ((unsigned)x0.y << 8) | ((unsigned)x0.z << 16) | ((unsigned)x0.w << 24);
        pk[1] = (unsigned)x1.x | ((unsigned)x1.y << 8) | ((unsigned)x1.z << 16) | ((unsigned)x1.w << 24);
        pk[2] = (unsigned)x2.x | ((unsigned)x2.y << 8) | ((unsigned)x2.z << 16) | ((unsigned)x2.w << 24);
        pk[3] = (unsigned)x3.x | ((unsigned)x3.y << 8) | ((unsigned)x3.z << 16) | ((unsigned)x3.w << 24);

        // kick off the word-embedding gather early (independent of conv)
        const int wi = Xword[w];
        const float4* src = reinterpret_cast<const float4*>(wemb + (size_t)wi * DEMB);
        float4* dst = reinterpret_cast<float4*>(out + (size_t)w * OUTW + CO);
        float4 e0, e1;
        const int j0 = j_lo + lane;
        const int j1 = j_lo + 32 + lane;
        const bool p0 = (j0 < j_hi);
        const bool p1 = (j1 < j_hi);
        if (p0) e0 = src[j0];
        if (p1) e1 = src[j1];

        // carry-chain sliding window:
        //   y[t] = M2[x_t] + c1,  c1' = M1[x_t] + c0,  c0' = M0[x_t]
        H4 maxs, c0 = zero, c1 = zero;
#pragma unroll
        for (int t = 0; t < 16; ++t) {
            const int cc = (pk[t >> 2] >> ((t & 3) * 8)) & 0xFF;
            const char* rowp = Ms_lane + cc * 768;
            H4 m0 = *reinterpret_cast<const H4*>(rowp);
            H4 m1 = *reinterpret_cast<const H4*>(rowp + 256);
            H4 m2 = *reinterpret_cast<const H4*>(rowp + 512);
            H4 y  = h4add(m2, c1);
            maxs  = (t == 0) ? y : h4max(maxs, y);
            c1 = h4add(m1, c0);
            c0 = m0;
        }
        maxs = h4max(maxs, c1);   // t = 16
        maxs = h4max(maxs, c0);   // t = 17

        // fp32 bias + relu + store
        float2 f0 = __half22float2(maxs.a);
        float2 f1 = __half22float2(maxs.b);
        float4 r;
        r.x = fmaxf(f0.x + b4.x, 0.f);
        r.y = fmaxf(f0.y + b4.y, 0.f);
        r.z = fmaxf(f1.x + b4.z, 0.f);
        r.w = fmaxf(f1.y + b4.w, 0.f);
        *reinterpret_cast<float4*>(out + (size_t)w * OUTW + o_base + lane * 4) = r;

        // complete this half's share of the embedding copy
        if (p0) dst[j0] = e0;
        if (p1) dst[j1] = e1;
    }
}

// ---------------------------------------------------------------------------
// Launch
// ---------------------------------------------------------------------------
extern "C" void kernel_launch(void* const* d_in, const int* in_sizes, int n_in,
                              void* d_out, int out_size) {
    const int*   X        = (const int*)  d_in[0];   // [16384,16]
    const int*   X_word   = (const int*)  d_in[1];   // [16384]
    const float* char_emb = (const float*)d_in[2];   // [128,64]
    const float* conv_w   = (const float*)d_in[3];   // [256,64,3]
    const float* conv_b   = (const float*)d_in[4];   // [256]
    const float* word_emb = (const float*)d_in[5];   // [50000,300]
    float*       out      = (float*)d_out;           // [16384,556]

    build_tables_kernel<<<256, 128>>>(char_emb, conv_w);

    const int smem = 128 * 768;                       // 98304 (96 KB)
    cudaFuncSetAttribute(wordchar_main_kernel,
                         cudaFuncAttributeMaxDynamicSharedMemorySize, smem);
    dim3 grid(148, 2);
    wordchar_main_kernel<<<grid, 640, smem>>>(X, X_word, conv_b, word_emb, out);
}